// round 4
// baseline (speedup 1.0000x reference)
#include <cuda_runtime.h>
#include <math.h>

#define NB 8
#define NT 2048
#define ND 1024
#define NP 512
#define NS 256
#define NH 256
#define TAU1F 0.5f

// -------- scratch (device globals; no runtime allocation) --------
__device__ float g_H[NB * NT * NH];        // relu(tokens@w1)   16 MB
__device__ float g_q[NB * NT * NS];        // tokens@wq         16 MB
__device__ float g_scores[NB * NT];
__device__ float g_sscore[NB * NP];        // top-512 sorted scores (desc)
__device__ int   g_gidx[NB * NP];          // global token row of sorted order
__device__ int   g_nhas[NB];
__device__ float g_summ[NB * NP * NS];     // summaries          4 MB
__device__ float g_k[NB * NP * NS];        //                    4 MB
__device__ float g_v[NB * NP * ND];        //                   16 MB
__device__ float g_attn[NB * NT * NP];     //                   33.5 MB
__device__ int   g_counts[NB];

// ================= generic fp32 SGEMM: C = A @ B (64x64 tile) ================
// BM=BN=64, BK=16, 256 threads, 4x4 microtile, float4 global+shared paths.
// COMP: compensated (TwoSum + FMA-error) accumulation for near-exact results.
template<bool TRANSB, bool RELU, bool GATHER, bool COMP>
__global__ void __launch_bounds__(256) sgemm_kernel(
    const float* __restrict__ A, const float* __restrict__ B, float* __restrict__ C,
    int M, int N, int K, int lda, int ldb, int ldc,
    long sA, long sB, long sC, const int* __restrict__ gidx)
{
    const int BM = 64, BN = 64, BK = 16;
    __shared__ float As[BK][BM + 4];
    __shared__ float Bs[BK][BN + 4];
    int z = blockIdx.z;
    A += (long)z * sA; B += (long)z * sB; C += (long)z * sC;
    int row0 = blockIdx.y * BM;
    int col0 = blockIdx.x * BN;
    int t = threadIdx.x;

    int aRow = t >> 2, aK4 = (t & 3) * 4;
    long aBase;
    if (GATHER) aBase = (long)gidx[row0 + aRow] * lda + aK4;
    else        aBase = (long)(row0 + aRow) * lda + aK4;

    int ty = t >> 4, tx = t & 15;
    float acc[4][4] = {};
    float cmp[4][4] = {};

    for (int k0 = 0; k0 < K; k0 += BK) {
        float4 av = *(const float4*)(A + aBase + k0);
        As[aK4 + 0][aRow] = av.x;
        As[aK4 + 1][aRow] = av.y;
        As[aK4 + 2][aRow] = av.z;
        As[aK4 + 3][aRow] = av.w;
        if (TRANSB) {
            int bN = t >> 2, bK4 = (t & 3) * 4;
            float4 bv = *(const float4*)(B + (long)(col0 + bN) * ldb + k0 + bK4);
            Bs[bK4 + 0][bN] = bv.x;
            Bs[bK4 + 1][bN] = bv.y;
            Bs[bK4 + 2][bN] = bv.z;
            Bs[bK4 + 3][bN] = bv.w;
        } else {
            int bK = t >> 4, bN4 = (t & 15) * 4;
            float4 bv = *(const float4*)(B + (long)(k0 + bK) * ldb + col0 + bN4);
            *(float4*)&Bs[bK][bN4] = bv;
        }
        __syncthreads();
        #pragma unroll
        for (int kk = 0; kk < BK; kk++) {
            float4 ra = *(const float4*)&As[kk][ty * 4];
            float4 rb = *(const float4*)&Bs[kk][tx * 4];
            float aa[4] = {ra.x, ra.y, ra.z, ra.w};
            float bb[4] = {rb.x, rb.y, rb.z, rb.w};
            #pragma unroll
            for (int i = 0; i < 4; i++)
                #pragma unroll
                for (int j = 0; j < 4; j++) {
                    if (COMP) {
                        // p + ep = a*b exactly; TwoSum(acc, p); fold errors into cmp
                        float p  = __fmul_rn(aa[i], bb[j]);
                        float ep = __fmaf_rn(aa[i], bb[j], -p);
                        float s  = __fadd_rn(acc[i][j], p);
                        float zz = __fsub_rn(s, acc[i][j]);
                        float es = __fadd_rn(__fsub_rn(acc[i][j], __fsub_rn(s, zz)),
                                             __fsub_rn(p, zz));
                        acc[i][j] = s;
                        cmp[i][j] = __fadd_rn(cmp[i][j], __fadd_rn(ep, es));
                    } else {
                        acc[i][j] += aa[i] * bb[j];
                    }
                }
        }
        __syncthreads();
    }
    #pragma unroll
    for (int i = 0; i < 4; i++) {
        float4 o;
        if (COMP) {
            o.x = __fadd_rn(acc[i][0], cmp[i][0]);
            o.y = __fadd_rn(acc[i][1], cmp[i][1]);
            o.z = __fadd_rn(acc[i][2], cmp[i][2]);
            o.w = __fadd_rn(acc[i][3], cmp[i][3]);
        } else {
            o.x = acc[i][0]; o.y = acc[i][1]; o.z = acc[i][2]; o.w = acc[i][3];
        }
        if (RELU) {
            o.x = fmaxf(o.x, 0.f); o.y = fmaxf(o.y, 0.f);
            o.z = fmaxf(o.z, 0.f); o.w = fmaxf(o.w, 0.f);
        }
        *(float4*)&C[(long)(row0 + ty * 4 + i) * ldc + col0 + tx * 4] = o;
    }
}

// ================= fp32 SGEMM: C = A @ B (128x64 tile, 8x4 microtile) ========
// BM=128, BN=64, BK=16, 256 threads. Higher FMA:LDS ratio (2.67 flop/float)
// than the 64x64 tile; used for the large plain GEMMs. M%128==0, N%64==0,
// K%16==0 required.
template<bool TRANSB>
__global__ void __launch_bounds__(256) sgemm128_kernel(
    const float* __restrict__ A, const float* __restrict__ B, float* __restrict__ C,
    int M, int N, int K, int lda, int ldb, int ldc,
    long sA, long sB, long sC)
{
    const int BM = 128, BN = 64, BK = 16;
    __shared__ float As[BK][BM + 4];
    __shared__ float Bs[BK][BN + 4];
    int z = blockIdx.z;
    A += (long)z * sA; B += (long)z * sB; C += (long)z * sC;
    int row0 = blockIdx.y * BM;
    int col0 = blockIdx.x * BN;
    int t = threadIdx.x;

    // A loads: 128 rows x 16 k = 512 float4; 2 per thread
    int aRow = t >> 1, aK8 = (t & 1) * 8;
    long aBase = (long)(row0 + aRow) * lda + aK8;

    int ty = t >> 4, tx = t & 15;      // ty: 8-row group, tx: 4-col group
    float acc[8][4] = {};

    for (int k0 = 0; k0 < K; k0 += BK) {
        float4 a0 = *(const float4*)(A + aBase + k0);
        float4 a1 = *(const float4*)(A + aBase + k0 + 4);
        As[aK8 + 0][aRow] = a0.x;
        As[aK8 + 1][aRow] = a0.y;
        As[aK8 + 2][aRow] = a0.z;
        As[aK8 + 3][aRow] = a0.w;
        As[aK8 + 4][aRow] = a1.x;
        As[aK8 + 5][aRow] = a1.y;
        As[aK8 + 6][aRow] = a1.z;
        As[aK8 + 7][aRow] = a1.w;
        if (TRANSB) {
            int bN = t >> 2, bK4 = (t & 3) * 4;
            float4 bv = *(const float4*)(B + (long)(col0 + bN) * ldb + k0 + bK4);
            Bs[bK4 + 0][bN] = bv.x;
            Bs[bK4 + 1][bN] = bv.y;
            Bs[bK4 + 2][bN] = bv.z;
            Bs[bK4 + 3][bN] = bv.w;
        } else {
            int bK = t >> 4, bN4 = (t & 15) * 4;
            float4 bv = *(const float4*)(B + (long)(k0 + bK) * ldb + col0 + bN4);
            *(float4*)&Bs[bK][bN4] = bv;
        }
        __syncthreads();
        #pragma unroll
        for (int kk = 0; kk < BK; kk++) {
            float4 ra0 = *(const float4*)&As[kk][ty * 8];
            float4 ra1 = *(const float4*)&As[kk][ty * 8 + 4];
            float4 rb  = *(const float4*)&Bs[kk][tx * 4];
            float aa[8] = {ra0.x, ra0.y, ra0.z, ra0.w, ra1.x, ra1.y, ra1.z, ra1.w};
            float bb[4] = {rb.x, rb.y, rb.z, rb.w};
            #pragma unroll
            for (int i = 0; i < 8; i++)
                #pragma unroll
                for (int j = 0; j < 4; j++)
                    acc[i][j] += aa[i] * bb[j];
        }
        __syncthreads();
    }
    #pragma unroll
    for (int i = 0; i < 8; i++) {
        float4 o;
        o.x = acc[i][0]; o.y = acc[i][1]; o.z = acc[i][2]; o.w = acc[i][3];
        *(float4*)&C[(long)(row0 + ty * 8 + i) * ldc + col0 + tx * 4] = o;
    }
}

// ========= scores = sigmoid(H @ w2), one warp per token, fp64 accumulate =====
__global__ void score_kernel(const float* __restrict__ w2)
{
    int gw = (blockIdx.x * blockDim.x + threadIdx.x) >> 5;
    int lane = threadIdx.x & 31;
    if (gw >= NB * NT) return;
    const float* h = g_H + (long)gw * NH;
    double acc = 0.0;
    #pragma unroll
    for (int i = 0; i < NH / 32; i++)
        acc = fma((double)h[lane + 32 * i], (double)w2[lane + 32 * i], acc);
    #pragma unroll
    for (int o = 16; o > 0; o >>= 1) acc += __shfl_xor_sync(0xffffffffu, acc, o);
    if (lane == 0) g_scores[gw] = (float)(1.0 / (1.0 + exp(-acc)));
}

// ================= per-batch stable descending sort (bitonic, tie=index asc) =
__global__ void __launch_bounds__(1024) sort_kernel()
{
    __shared__ float ss[NT];
    __shared__ int   si[NT];
    __shared__ int   cnt;
    int b = blockIdx.x, t = threadIdx.x;
    for (int i = t; i < NT; i += 1024) { ss[i] = g_scores[b * NT + i]; si[i] = i; }
    if (t == 0) cnt = 0;
    __syncthreads();
    for (int k = 2; k <= NT; k <<= 1)
        for (int j = k >> 1; j > 0; j >>= 1) {
            for (int i = t; i < NT; i += 1024) {
                int ixj = i ^ j;
                if (ixj > i) {
                    float s1 = ss[i], s2 = ss[ixj];
                    int   i1 = si[i], i2 = si[ixj];
                    // desired order: score desc, index asc (stable argsort(-scores))
                    bool bef12 = (s1 > s2) || (s1 == s2 && i1 < i2);
                    bool bef21 = (s2 > s1) || (s2 == s1 && i2 < i1);
                    bool dir = ((i & k) == 0);
                    bool doswap = dir ? bef21 : bef12;
                    if (doswap) { ss[i] = s2; ss[ixj] = s1; si[i] = i2; si[ixj] = i1; }
                }
            }
            __syncthreads();
        }
    if (t < NP) {
        g_sscore[b * NP + t] = ss[t];
        g_gidx[b * NP + t]   = b * NT + si[t];
        if (ss[t] > TAU1F) atomicAdd(&cnt, 1);
    }
    __syncthreads();
    if (t == 0) g_nhas[b] = cnt;
}

// ================= pool update: closed-form insert + streaming replace-min ===
// Replace i fires iff imp_{j0+i} > m_i (m = sorted ascending post-insert pri);
// first failure ends the stream (imps descend, pool-min non-decreasing).
// The pool-filling token (j0) double-writes (insert at slot P-1 AND replace),
// exactly as the reference scan does.
__global__ void __launch_bounds__(512) update_kernel(
    const float* __restrict__ pool_in, const float* __restrict__ pri_in,
    const int* __restrict__ counts_in,
    float* __restrict__ pool_out, float* __restrict__ pri_out,
    float* __restrict__ counts_out_f)
{
    __shared__ float pri[NP];
    __shared__ float skey[NP];
    __shared__ int   sidx[NP];
    __shared__ int   sh_r;
    int b = blockIdx.x, t = threadIdx.x;
    const float4* pb = (const float4*)(pool_in  + (long)b * NP * NS);
    float4*       po = (float4*)      (pool_out + (long)b * NP * NS);
    const float4* sm = (const float4*)(g_summ   + (long)b * NP * NS);

    // base copy of pool into output region
    for (int i = t; i < NP * NS / 4; i += 512) po[i] = pb[i];

    int c0 = counts_in[b]; c0 = max(0, min(c0, NP));
    int nh = g_nhas[b];
    int nins = min(nh, NP - c0);
    const float* ss = g_sscore + b * NP;

    // post-insert priorities
    pri[t] = (t >= c0 && t < c0 + nins) ? ss[t - c0] : pri_in[b * NP + t];
    __syncthreads();   // base copy done + pri built

    // parallel inserts: summary row j -> slot c0+j
    for (int v = t; v < nins * (NS / 4); v += 512) {
        int j = v >> 6, cc = v & 63;
        po[(c0 + j) * (NS / 4) + cc] = sm[j * (NS / 4) + cc];
    }
    int cf = c0 + nins;

    if (cf == NP) {
        int j0 = max(0, NP - c0 - 1);
        int L  = nh - j0;     // stream length (>=1 when pool full)
        skey[t] = pri[t]; sidx[t] = t;
        if (t == 0) sh_r = L;
        __syncthreads();
        // bitonic ascending by (pri, slot) -> m-sequence with argmin tie-break
        for (int k = 2; k <= NP; k <<= 1)
            for (int j = k >> 1; j > 0; j >>= 1) {
                int i = t, ixj = i ^ j;
                if (ixj > i) {
                    float s1 = skey[i], s2 = skey[ixj];
                    int   i1 = sidx[i], i2 = sidx[ixj];
                    bool bef21 = (s2 < s1) || (s2 == s1 && i2 < i1);
                    bool bef12 = (s1 < s2) || (s1 == s2 && i1 < i2);
                    bool dir = ((i & k) == 0);
                    bool doswap = dir ? bef21 : bef12;
                    if (doswap) { skey[i] = s2; skey[ixj] = s1; sidx[i] = i2; sidx[ixj] = i1; }
                }
                __syncthreads();
            }
        if (t < L) {
            float imp = ss[j0 + t];
            if (!(imp > skey[t])) atomicMin(&sh_r, t);
        }
        __syncthreads();
        int r = sh_r;
        if (t < r) pri[sidx[t]] = ss[j0 + t];
        // replaced slots never coincide with inserted slots (strict-descending
        // imps can never beat an inserted priority), so no write ordering needed
        for (int v = t; v < r * (NS / 4); v += 512) {
            int j = v >> 6, cc = v & 63;
            po[sidx[j] * (NS / 4) + cc] = sm[(j0 + j) * (NS / 4) + cc];
        }
        __syncthreads();
    }
    pri_out[b * NP + t] = pri[t];
    if (t == 0) { g_counts[b] = cf; counts_out_f[b] = (float)cf; }
}

// ================= masked softmax over pool dim, one warp per (b,t) row ======
__global__ void softmax_kernel()
{
    int gw = (blockIdx.x * blockDim.x + threadIdx.x) >> 5;
    int lane = threadIdx.x & 31;
    if (gw >= NB * NT) return;
    int b = gw / NT;
    float* row = g_attn + (long)gw * NP;
    int c = g_counts[b];
    if (c <= 0) {
        #pragma unroll
        for (int i = 0; i < NP / 32; i++) row[lane + 32 * i] = 0.f;
        return;
    }
    const float scale = 0.0625f;  // 1/sqrt(256)
    float v[NP / 32];
    float m = -INFINITY;
    #pragma unroll
    for (int i = 0; i < NP / 32; i++) {
        int p = lane + 32 * i;
        v[i] = (p < c) ? row[p] * scale : -INFINITY;
        m = fmaxf(m, v[i]);
    }
    #pragma unroll
    for (int o = 16; o > 0; o >>= 1) m = fmaxf(m, __shfl_xor_sync(0xffffffffu, m, o));
    float s = 0.f;
    #pragma unroll
    for (int i = 0; i < NP / 32; i++) {
        int p = lane + 32 * i;
        float e = (p < c) ? expf(v[i] - m) : 0.f;
        v[i] = e; s += e;
    }
    #pragma unroll
    for (int o = 16; o > 0; o >>= 1) s += __shfl_xor_sync(0xffffffffu, s, o);
    float inv = 1.f / s;
    #pragma unroll
    for (int i = 0; i < NP / 32; i++) row[lane + 32 * i] = v[i] * inv;
}

// ================= host orchestration =======================================
extern "C" void kernel_launch(void* const* d_in, const int* in_sizes, int n_in,
                              void* d_out, int out_size)
{
    const float* tokens = (const float*)d_in[0];
    const float* pool   = (const float*)d_in[1];
    const float* prio   = (const float*)d_in[2];
    const int*   counts = (const int*)  d_in[3];
    const float* w1     = (const float*)d_in[4];
    const float* w2     = (const float*)d_in[5];
    const float* w_sum  = (const float*)d_in[6];
    const float* wq     = (const float*)d_in[7];
    const float* wk     = (const float*)d_in[8];
    const float* wv     = (const float*)d_in[9];
    (void)in_sizes; (void)n_in; (void)out_size;

    float* out      = (float*)d_out;
    float* out_ret  = out;                                   // [8,2048,1024]
    float* out_pool = out + (long)NB * NT * ND;              // [8,512,256]
    float* out_pri  = out_pool + (long)NB * NP * NS;         // [8,512]
    float* out_cnt  = out_pri + (long)NB * NP;               // [8] as float

    float *pH, *pQ, *pSumm, *pK, *pV, *pAttn;
    int *pGidx;
    cudaGetSymbolAddress((void**)&pH,    g_H);
    cudaGetSymbolAddress((void**)&pQ,    g_q);
    cudaGetSymbolAddress((void**)&pSumm, g_summ);
    cudaGetSymbolAddress((void**)&pK,    g_k);
    cudaGetSymbolAddress((void**)&pV,    g_v);
    cudaGetSymbolAddress((void**)&pAttn, g_attn);
    cudaGetSymbolAddress((void**)&pGidx, g_gidx);

    dim3 blk(256);

    // 1) H = relu(tokens @ w1)  [16384,1024]x[1024,256]  -- compensated fp32
    sgemm_kernel<false, true, false, true><<<dim3(NH / 64, (NB * NT) / 64, 1), blk>>>(
        tokens, w1, pH, NB * NT, NH, ND, ND, NH, NH, 0, 0, 0, nullptr);
    // 2) scores = sigmoid(H @ w2)  -- fp64 accumulate
    score_kernel<<<(NB * NT * 32 + 255) / 256, 256>>>(w2);
    // 3) q = tokens @ wq  (independent of sort/update; issue early)
    sgemm128_kernel<false><<<dim3(NS / 64, (NB * NT) / 128, 1), blk>>>(
        tokens, wq, pQ, NB * NT, NS, ND, ND, NS, NS, 0, 0, 0);
    // 4) per-batch stable descending sort
    sort_kernel<<<NB, 1024>>>();
    // 5) summaries = gather(tokens) @ w_sum   [4096,1024]x[1024,256]
    sgemm_kernel<false, false, true, false><<<dim3(NS / 64, (NB * NP) / 64, 1), blk>>>(
        tokens, w_sum, pSumm, NB * NP, NS, ND, ND, NS, NS, 0, 0, 0, pGidx);
    // 6) pool/priority/counts update (writes final pool/pri/counts into d_out)
    update_kernel<<<NB, 512>>>(pool, prio, counts, out_pool, out_pri, out_cnt);
    // 7) k = pool_final @ wk             [4096,256]x[256,256]
    sgemm128_kernel<false><<<dim3(NS / 64, (NB * NP) / 128, 1), blk>>>(
        out_pool, wk, pK, NB * NP, NS, NS, NS, NS, NS, 0, 0, 0);
    // 8) v = pool_final @ wv             [4096,256]x[256,1024]
    sgemm128_kernel<false><<<dim3(ND / 64, (NB * NP) / 128, 1), blk>>>(
        out_pool, wv, pV, NB * NP, ND, NS, NS, ND, ND, 0, 0, 0);
    // 9) attn = q @ k^T (batched)  per batch [2048,256]x[512,256]^T
    sgemm128_kernel<true><<<dim3(NP / 64, NT / 128, NB), blk>>>(
        pQ, pK, pAttn, NT, NP, NS, NS, NS, NP,
        (long)NT * NS, (long)NP * NS, (long)NT * NP);
    // 10) masked softmax (+1/16 scale, nan_to_num for empty pools)
    softmax_kernel<<<(NB * NT * 32 + 255) / 256, 256>>>();
    // 11) retrieved = attn @ v (batched) -> d_out   per batch [2048,512]x[512,1024]
    sgemm128_kernel<false><<<dim3(ND / 64, NT / 128, NB), blk>>>(
        pAttn, pV, out_ret, NT, ND, NP, NP, ND, ND,
        (long)NT * NP, (long)NP * ND, (long)NT * ND);
}